// round 15
// baseline (speedup 1.0000x reference)
#include <cuda_runtime.h>
#include <cuda_bf16.h>
#include <cuda_fp16.h>
#include <math.h>
#include <stdint.h>

// Problem constants
#define NMAX 50000
#define EMAX 800000
#define FDIM 128
#define SCAN_BLK 512
#define MPAD 128   // row padding so cp.async can safely over-read the last tile

// ---------------- device scratch ----------------
__device__ __half g_qh[NMAX * FDIM];     // q * (1/sqrt(C)), fp16
__device__ __half g_skh[NMAX * FDIM];    // skip projection, fp16
// Interleaved kv: per node 256 halves; lane-l group at l*8: [k(4l..4l+3) | v(4l..4l+3)]
__device__ __half g_kv[NMAX * 256];
// fp16 operands
__device__ __half g_xh[(NMAX + MPAD) * FDIM];
__device__ __half g_wh[512 * FDIM];
__device__ int    g_count[NMAX];
__device__ int    g_rowptr[NMAX + 1];
__device__ int    g_fill[NMAX];
__device__ int    g_esrc[EMAX];
__device__ int    g_bsum[1024];
__device__ int    g_boff[1024];

// ---------------- helpers ----------------
__device__ __forceinline__ uint32_t smem_u32(const void* p) {
    uint32_t a;
    asm("{ .reg .u64 t; cvta.to.shared.u64 t, %1; cvt.u32.u64 %0, t; }" : "=r"(a) : "l"(p));
    return a;
}
__device__ __forceinline__ void cp16(uint32_t dst, const void* src) {
    asm volatile("cp.async.cg.shared.global [%0], [%1], 16;" :: "r"(dst), "l"(src));
}
// L1-enabled variant for the scattered kv gather (possible same-SM reuse)
__device__ __forceinline__ void cp16ca(uint32_t dst, const void* src) {
    asm volatile("cp.async.ca.shared.global [%0], [%1], 16;" :: "r"(dst), "l"(src));
}
// packed f32x2 ops (Blackwell)
__device__ __forceinline__ uint64_t pack2(float lo, float hi) {
    uint64_t d;
    asm("mov.b64 %0, {%1,%2};" : "=l"(d) : "f"(lo), "f"(hi));
    return d;
}
__device__ __forceinline__ void unpack2(uint64_t d, float& lo, float& hi) {
    asm("mov.b64 {%0,%1}, %2;" : "=f"(lo), "=f"(hi) : "l"(d));
}
__device__ __forceinline__ uint64_t mul2(uint64_t a, uint64_t b) {
    uint64_t d;
    asm("mul.rn.f32x2 %0, %1, %2;" : "=l"(d) : "l"(a), "l"(b));
    return d;
}
__device__ __forceinline__ uint64_t fma2(uint64_t a, uint64_t b, uint64_t c) {
    uint64_t d;
    asm("fma.rn.f32x2 %0, %1, %2, %3;" : "=l"(d) : "l"(a), "l"(b), "l"(c));
    return d;
}

// ---------------- 0) convert x and W to fp16 ----------------
__global__ void split_all(const float* __restrict__ x,
                          const float* __restrict__ Wq, const float* __restrict__ Wk,
                          const float* __restrict__ Wv, const float* __restrict__ Ws,
                          int n)
{
    const int nx = n * (FDIM / 4);
    const int i = blockIdx.x * blockDim.x + threadIdx.x;
    if (i < nx) {
        float4 v = *(const float4*)(x + (size_t)i * 4);
        ushort4 h4;
        h4.x = __half_as_ushort(__float2half_rn(v.x));
        h4.y = __half_as_ushort(__float2half_rn(v.y));
        h4.z = __half_as_ushort(__float2half_rn(v.z));
        h4.w = __half_as_ushort(__float2half_rn(v.w));
        *(ushort4*)(g_xh + (size_t)i * 4) = h4;
    } else {
        const int j = i - nx;                 // over 512*32 float4s
        if (j >= 512 * (FDIM / 4)) return;
        const int m = j >> 12;
        const int r = j & 4095;
        const float* W = (m == 0) ? Wq : (m == 1) ? Wk : (m == 2) ? Wv : Ws;
        float4 v = *(const float4*)(W + (size_t)r * 4);
        ushort4 h4;
        h4.x = __half_as_ushort(__float2half_rn(v.x));
        h4.y = __half_as_ushort(__float2half_rn(v.y));
        h4.z = __half_as_ushort(__float2half_rn(v.z));
        h4.w = __half_as_ushort(__float2half_rn(v.w));
        *(ushort4*)(g_wh + (size_t)j * 4) = h4;
    }
}

// ---------------- 1) cp.async-pipelined fp16 mma GEMM (single pass, BK=32) ----------------
#define APAD32 40   // 80B row stride -> conflict-free frag loads
#define NT4 4       // 128 / 32

__device__ __forceinline__ void mma_fp16(float c[4], const uint32_t a[4], const uint32_t b[2]) {
    asm volatile(
        "mma.sync.aligned.m16n8k16.row.col.f32.f16.f16.f32 "
        "{%0,%1,%2,%3}, {%4,%5,%6,%7}, {%8,%9}, {%0,%1,%2,%3};"
        : "+f"(c[0]), "+f"(c[1]), "+f"(c[2]), "+f"(c[3])
        : "r"(a[0]), "r"(a[1]), "r"(a[2]), "r"(a[3]), "r"(b[0]), "r"(b[1]));
}

__global__ __launch_bounds__(256) void gemm_mma(
    const float* __restrict__ bq, const float* __restrict__ bk,
    const float* __restrict__ bv, const float* __restrict__ bs,
    int M)
{
    // [stage][array: A,B][128 rows * APAD32] = 40 KB
    __shared__ __half sm[2][2][128 * APAD32];

    const float* bias;
    switch (blockIdx.y) {
        case 0:  bias = bq; break;
        case 1:  bias = bk; break;
        case 2:  bias = bv; break;
        default: bias = bs; break;
    }
    const bool to_kv = (blockIdx.y == 1) || (blockIdx.y == 2);
    __half* outh = (blockIdx.y == 0) ? g_qh : g_skh;
    const int hsub = (blockIdx.y == 1) ? 0 : 4;
    const float oscale = (blockIdx.y == 0) ? 0.17677669529663687f : 1.0f;

    const int tid  = threadIdx.x;
    const int wid  = tid >> 5;
    const int lane = tid & 31;
    const int wm   = wid >> 2;
    const int wn   = wid & 3;
    const int m0   = blockIdx.x * 128;
    const int nb0  = blockIdx.y * 128;     // W row block
    const int qrow = lane >> 2;
    const int qk   = (lane & 3) * 2;

    // cp.async coords: per array per tile 512 chunks of 16B; 2 per thread
    const int f0 = tid, f1 = tid + 256;
    const int r0c = f0 >> 2, c0c = (f0 & 3) * 8;     // row, halves offset
    const int r1c = f1 >> 2, c1c = (f1 & 3) * 8;
    const uint32_t so0 = (uint32_t)(r0c * APAD32 + c0c) * 2;
    const uint32_t so1 = (uint32_t)(r1c * APAD32 + c1c) * 2;
    const size_t gaA0 = (size_t)(m0 + r0c) * FDIM + c0c;
    const size_t gaA1 = (size_t)(m0 + r1c) * FDIM + c1c;
    const size_t gaB0 = (size_t)(nb0 + r0c) * FDIM + c0c;
    const size_t gaB1 = (size_t)(nb0 + r1c) * FDIM + c1c;
    const uint32_t sb = smem_u32(&sm[0][0][0]);
    const uint32_t SA = 128 * APAD32 * 2;          // bytes per array
    const uint32_t SS = 2 * SA;                    // bytes per stage

    float c[4][4][4];
    #pragma unroll
    for (int mi = 0; mi < 4; mi++)
        #pragma unroll
        for (int nj = 0; nj < 4; nj++)
            #pragma unroll
            for (int r = 0; r < 4; r++) c[mi][nj][r] = 0.f;

    // prologue: tile 0 -> stage 0
    {
        cp16(sb + 0 * SA + so0, g_xh + gaA0);
        cp16(sb + 0 * SA + so1, g_xh + gaA1);
        cp16(sb + 1 * SA + so0, g_wh + gaB0);
        cp16(sb + 1 * SA + so1, g_wh + gaB1);
        asm volatile("cp.async.commit_group;");
    }

    for (int ct = 0; ct < NT4; ct++) {
        const int s = ct & 1;
        if (ct + 1 < NT4) {
            const int kt = (ct + 1) * 32;
            const uint32_t st = sb + ((ct + 1) & 1) * SS;
            cp16(st + 0 * SA + so0, g_xh + gaA0 + kt);
            cp16(st + 0 * SA + so1, g_xh + gaA1 + kt);
            cp16(st + 1 * SA + so0, g_wh + gaB0 + kt);
            cp16(st + 1 * SA + so1, g_wh + gaB1 + kt);
            asm volatile("cp.async.commit_group;");
            asm volatile("cp.async.wait_group 1;");
        } else {
            asm volatile("cp.async.wait_group 0;");
        }
        __syncthreads();

        const __half* Ab = sm[s][0];
        const __half* Bb = sm[s][1];
        #pragma unroll
        for (int ks = 0; ks < 2; ks++) {
            const int kb = ks * 16 + qk;
            uint32_t a[4][4], b[4][2];
            #pragma unroll
            for (int mi = 0; mi < 4; mi++) {
                const int row = wm * 64 + mi * 16 + qrow;
                a[mi][0] = *(const uint32_t*)(Ab + row * APAD32 + kb);
                a[mi][1] = *(const uint32_t*)(Ab + (row + 8) * APAD32 + kb);
                a[mi][2] = *(const uint32_t*)(Ab + row * APAD32 + kb + 8);
                a[mi][3] = *(const uint32_t*)(Ab + (row + 8) * APAD32 + kb + 8);
            }
            #pragma unroll
            for (int nj = 0; nj < 4; nj++) {
                const int col = wn * 32 + nj * 8 + qrow;
                b[nj][0] = *(const uint32_t*)(Bb + col * APAD32 + kb);
                b[nj][1] = *(const uint32_t*)(Bb + col * APAD32 + kb + 8);
            }
            #pragma unroll
            for (int mi = 0; mi < 4; mi++)
                #pragma unroll
                for (int nj = 0; nj < 4; nj++)
                    mma_fp16(c[mi][nj], a[mi], b[nj]);
        }
        __syncthreads();
    }

    float2 bj[4];
    #pragma unroll
    for (int nj = 0; nj < 4; nj++) {
        const int col = wn * 32 + nj * 8 + (lane & 3) * 2;
        bj[nj] = *(const float2*)(bias + col);
    }
    #pragma unroll
    for (int mi = 0; mi < 4; mi++) {
        const int r0 = m0 + wm * 64 + mi * 16 + qrow;
        #pragma unroll
        for (int nj = 0; nj < 4; nj++) {
            const int col = wn * 32 + nj * 8 + (lane & 3) * 2;
            const float v00 = (c[mi][nj][0] + bj[nj].x) * oscale;
            const float v01 = (c[mi][nj][1] + bj[nj].y) * oscale;
            const float v10 = (c[mi][nj][2] + bj[nj].x) * oscale;
            const float v11 = (c[mi][nj][3] + bj[nj].y) * oscale;
            if (to_kv) {
                const int off = ((col >> 2) << 3) + (col & 3) + hsub;
                if (r0 < M)
                    *(__half2*)(g_kv + (size_t)r0 * 256 + off) = __floats2half2_rn(v00, v01);
                if (r0 + 8 < M)
                    *(__half2*)(g_kv + (size_t)(r0 + 8) * 256 + off) = __floats2half2_rn(v10, v11);
            } else {
                if (r0 < M)
                    *(__half2*)(outh + (size_t)r0 * 128 + col) = __floats2half2_rn(v00, v01);
                if (r0 + 8 < M)
                    *(__half2*)(outh + (size_t)(r0 + 8) * 128 + col) = __floats2half2_rn(v10, v11);
            }
        }
    }
}

// ---------------- 2) CSR build ----------------
__global__ void zero_counts(int n)
{
    int i = blockIdx.x * blockDim.x + threadIdx.x;
    if (i < n) g_count[i] = 0;
}

__global__ void hist_kernel(const int* __restrict__ ei, int e)
{
    int i = blockIdx.x * blockDim.x + threadIdx.x;
    if (i < e) atomicAdd(&g_count[ei[e + i]], 1);
}

__global__ void scan_blocks(int n)
{
    __shared__ int sh[SCAN_BLK];
    const int t = threadIdx.x;
    const int i = blockIdx.x * SCAN_BLK + t;
    const int v = (i < n) ? g_count[i] : 0;
    sh[t] = v;
    __syncthreads();
    #pragma unroll
    for (int off = 1; off < SCAN_BLK; off <<= 1) {
        int u = (t >= off) ? sh[t - off] : 0;
        __syncthreads();
        sh[t] += u;
        __syncthreads();
    }
    if (i < n) g_rowptr[i] = sh[t] - v;
    if (t == SCAN_BLK - 1) g_bsum[blockIdx.x] = sh[t];
}

__global__ void scan_tops(int nb, int n)
{
    __shared__ int sh[SCAN_BLK];
    const int t = threadIdx.x;
    const int v = (t < nb) ? g_bsum[t] : 0;
    sh[t] = v;
    __syncthreads();
    #pragma unroll
    for (int off = 1; off < SCAN_BLK; off <<= 1) {
        int u = (t >= off) ? sh[t - off] : 0;
        __syncthreads();
        sh[t] += u;
        __syncthreads();
    }
    g_boff[t] = sh[t] - v;
    if (t == SCAN_BLK - 1) g_rowptr[n] = sh[t];
}

__global__ void add_offsets(int n)
{
    const int i = blockIdx.x * blockDim.x + threadIdx.x;
    if (i < n) {
        const int r = g_rowptr[i] + g_boff[i / SCAN_BLK];
        g_rowptr[i] = r;
        g_fill[i]   = r;
    }
}

__global__ void scatter_kernel(const int* __restrict__ ei, int e)
{
    int i = blockIdx.x * blockDim.x + threadIdx.x;
    if (i < e) {
        int dst  = ei[e + i];
        int slot = atomicAdd(&g_fill[dst], 1);
        g_esrc[slot] = ei[i];
    }
}

// ---------------- 3) fused attention aggregation: cp.async gather pipeline ----------------
#define EA_WARPS 8
__global__ __launch_bounds__(256) void edge_attn(float* __restrict__ out, int n)
{
    __shared__ char kvbuf[EA_WARPS][2][2048];   // 32 KB: 2 stages x 4 edges x 512B per warp

    const int wInB = threadIdx.x >> 5;
    const int lane = threadIdx.x & 31;
    const int node = blockIdx.x * EA_WARPS + wInB;
    if (node >= n) return;

    // q already scaled by 1/sqrt(C) in the GEMM epilogue; packed f32x2
    uint64_t q01, q23;
    {
        const uint2 qu = *(const uint2*)(g_qh + (size_t)node * 128 + lane * 4);
        const float2 qa = __half22float2(*(const __half2*)&qu.x);
        const float2 qb = __half22float2(*(const __half2*)&qu.y);
        q01 = pack2(qa.x, qa.y);
        q23 = pack2(qb.x, qb.y);
    }

    uint64_t acc01 = 0ull, acc23 = 0ull;   // packed (0.f, 0.f)
    float den = 0.f;

    const int beg = g_rowptr[node];
    const int end = g_rowptr[node + 1];
    const int ngrp = (end - beg) >> 2;
    const uint32_t sbase = smem_u32(&kvbuf[wInB][0][0]);

    int sB[4];
    if (ngrp > 0) {
        int sA[4];
        #pragma unroll
        for (int u = 0; u < 4; u++) sA[u] = __ldg(&g_esrc[beg + u]);
        #pragma unroll
        for (int u = 0; u < 4; u++)
            cp16ca(sbase + u * 512 + lane * 16, g_kv + (size_t)sA[u] * 256 + lane * 8);
        asm volatile("cp.async.commit_group;");
        if (ngrp > 1) {
            #pragma unroll
            for (int u = 0; u < 4; u++) sB[u] = __ldg(&g_esrc[beg + 4 + u]);
        }
    }

    for (int g = 0; g < ngrp; g++) {
        if (g + 1 < ngrp) {
            const uint32_t st = sbase + ((g + 1) & 1) * 2048;
            #pragma unroll
            for (int u = 0; u < 4; u++)
                cp16ca(st + u * 512 + lane * 16, g_kv + (size_t)sB[u] * 256 + lane * 8);
            asm volatile("cp.async.commit_group;");
            if (g + 2 < ngrp) {
                #pragma unroll
                for (int u = 0; u < 4; u++) sB[u] = __ldg(&g_esrc[beg + (g + 2) * 4 + u]);
            }
            asm volatile("cp.async.wait_group 1;");
        } else {
            asm volatile("cp.async.wait_group 0;");
        }

        const uint32_t cur = sbase + (g & 1) * 2048;
        uint4 kv[4];
        #pragma unroll
        for (int u = 0; u < 4; u++) {
            asm("ld.shared.v4.u32 {%0,%1,%2,%3}, [%4];"
                : "=r"(kv[u].x), "=r"(kv[u].y), "=r"(kv[u].z), "=r"(kv[u].w)
                : "r"(cur + u * 512 + lane * 16));
        }
        float p[4];
        #pragma unroll
        for (int u = 0; u < 4; u++) {
            const float2 ka = __half22float2(*(const __half2*)&kv[u].x);
            const float2 kb = __half22float2(*(const __half2*)&kv[u].y);
            const uint64_t d = fma2(q23, pack2(kb.x, kb.y), mul2(q01, pack2(ka.x, ka.y)));
            float dlo, dhi;
            unpack2(d, dlo, dhi);
            p[u] = dlo + dhi;
        }
        #pragma unroll
        for (int u = 0; u < 4; u++) p[u] += __shfl_xor_sync(0xffffffffu, p[u], 1, 8);
        #pragma unroll
        for (int u = 0; u < 4; u++) p[u] += __shfl_xor_sync(0xffffffffu, p[u], 2, 8);
        #pragma unroll
        for (int u = 0; u < 4; u++) p[u] += __shfl_xor_sync(0xffffffffu, p[u], 4, 8);
        #pragma unroll
        for (int u = 0; u < 4; u++) {
            const float w = __expf(p[u]);
            const float2 va = __half22float2(*(const __half2*)&kv[u].z);
            const float2 vb = __half22float2(*(const __half2*)&kv[u].w);
            den += w;
            const uint64_t w2 = pack2(w, w);
            acc01 = fma2(w2, pack2(va.x, va.y), acc01);
            acc23 = fma2(w2, pack2(vb.x, vb.y), acc23);
        }
    }

    // tail (deg % 4) via direct loads
    for (int i = beg + ngrp * 4; i < end; i++) {
        const int s0 = __ldg(&g_esrc[i]);
        const uint4 kv0 = *(const uint4*)(g_kv + (size_t)s0 * 256 + lane * 8);
        const float2 ka = __half22float2(*(const __half2*)&kv0.x);
        const float2 kb = __half22float2(*(const __half2*)&kv0.y);
        const uint64_t d = fma2(q23, pack2(kb.x, kb.y), mul2(q01, pack2(ka.x, ka.y)));
        float dlo, dhi;
        unpack2(d, dlo, dhi);
        float p0 = dlo + dhi;
        p0 += __shfl_xor_sync(0xffffffffu, p0, 1, 8);
        p0 += __shfl_xor_sync(0xffffffffu, p0, 2, 8);
        p0 += __shfl_xor_sync(0xffffffffu, p0, 4, 8);
        const float w = __expf(p0);
        const float2 va = __half22float2(*(const __half2*)&kv0.z);
        const float2 vb = __half22float2(*(const __half2*)&kv0.w);
        den += w;
        const uint64_t w2 = pack2(w, w);
        acc01 = fma2(w2, pack2(va.x, va.y), acc01);
        acc23 = fma2(w2, pack2(vb.x, vb.y), acc23);
    }

    const float inv = (den > 0.f) ? (1.0f / den) : 0.f;
    float4 sk;
    {
        const uint2 su = *(const uint2*)(g_skh + (size_t)node * 128 + lane * 4);
        const float2 sa = __half22float2(*(const __half2*)&su.x);
        const float2 sb2 = __half22float2(*(const __half2*)&su.y);
        sk = make_float4(sa.x, sa.y, sb2.x, sb2.y);
    }
    float a0, a1, a2, a3;
    unpack2(acc01, a0, a1);
    unpack2(acc23, a2, a3);
    float4 o;
    o.x = fmaxf(fmaf(a0, inv, sk.x), 0.f);
    o.y = fmaxf(fmaf(a1, inv, sk.y), 0.f);
    o.z = fmaxf(fmaf(a2, inv, sk.z), 0.f);
    o.w = fmaxf(fmaf(a3, inv, sk.w), 0.f);
    *(float4*)(out + (size_t)node * 128 + lane * 4) = o;
}

// ---------------- host launcher ----------------
extern "C" void kernel_launch(void* const* d_in, const int* in_sizes, int n_in,
                              void* d_out, int out_size)
{
    const float* x  = (const float*)d_in[0];
    const int*   ei = (const int*)  d_in[1];
    const float* Wq = (const float*)d_in[2];
    const float* bq = (const float*)d_in[3];
    const float* Wk = (const float*)d_in[4];
    const float* bk = (const float*)d_in[5];
    const float* Wv = (const float*)d_in[6];
    const float* bv = (const float*)d_in[7];
    const float* Ws = (const float*)d_in[8];
    const float* bs = (const float*)d_in[9];
    float* out = (float*)d_out;

    const int n = in_sizes[0] / FDIM;   // 50000
    const int e = in_sizes[1] / 2;      // 800000
    const int nb = (n + SCAN_BLK - 1) / SCAN_BLK;

    // Side stream: CSR build overlaps convert + GEMM.
    cudaStream_t s2;
    cudaEvent_t ev0, ev1;
    cudaStreamCreateWithFlags(&s2, cudaStreamNonBlocking);
    cudaEventCreateWithFlags(&ev0, cudaEventDisableTiming);
    cudaEventCreateWithFlags(&ev1, cudaEventDisableTiming);

    cudaEventRecord(ev0, 0);
    cudaStreamWaitEvent(s2, ev0, 0);

    zero_counts<<<(n + 255) / 256, 256, 0, s2>>>(n);
    hist_kernel<<<(e + 255) / 256, 256, 0, s2>>>(ei, e);
    scan_blocks<<<nb, SCAN_BLK, 0, s2>>>(n);
    scan_tops<<<1, SCAN_BLK, 0, s2>>>(nb, n);
    add_offsets<<<(n + 255) / 256, 256, 0, s2>>>(n);
    scatter_kernel<<<(e + 255) / 256, 256, 0, s2>>>(ei, e);
    cudaEventRecord(ev1, s2);

    // fp16 convert, then pipelined GEMM, on main stream
    const int tot4 = n * (FDIM / 4) + 512 * (FDIM / 4);
    split_all<<<(tot4 + 255) / 256, 256>>>(x, Wq, Wk, Wv, Ws, n);
    dim3 gg((n + 127) / 128, 4);
    gemm_mma<<<gg, 256>>>(bq, bk, bv, bs, n);

    cudaStreamWaitEvent(0, ev1, 0);
    edge_attn<<<(n + EA_WARPS - 1) / EA_WARPS, 256>>>(out, n);
}

// round 16
// speedup vs baseline: 1.0740x; 1.0740x over previous
#include <cuda_runtime.h>
#include <cuda_bf16.h>
#include <cuda_fp16.h>
#include <math.h>
#include <stdint.h>

// Problem constants
#define NMAX 50000
#define EMAX 800000
#define FDIM 128
#define SCAN_BLK 512
#define MPAD 128   // row padding so cp.async can safely over-read the last tile

// ---------------- device scratch ----------------
__device__ __half g_qh[NMAX * FDIM];     // q * (1/sqrt(C)), fp16
__device__ __half g_skh[NMAX * FDIM];    // skip projection, fp16
// Interleaved kv: per node 256 halves; lane-l group at l*8: [k(4l..4l+3) | v(4l..4l+3)]
__device__ __half g_kv[NMAX * 256];
// fp16 operands
__device__ __half g_xh[(NMAX + MPAD) * FDIM];
__device__ __half g_wh[512 * FDIM];
__device__ int    g_count[NMAX];
__device__ int    g_rowptr[NMAX + 1];
__device__ int    g_fill[NMAX];
__device__ int    g_esrc[EMAX];
__device__ int    g_bsum[1024];
__device__ int    g_boff[1024];

// ---------------- helpers ----------------
__device__ __forceinline__ uint32_t smem_u32(const void* p) {
    uint32_t a;
    asm("{ .reg .u64 t; cvta.to.shared.u64 t, %1; cvt.u32.u64 %0, t; }" : "=r"(a) : "l"(p));
    return a;
}
__device__ __forceinline__ void cp16(uint32_t dst, const void* src) {
    asm volatile("cp.async.cg.shared.global [%0], [%1], 16;" :: "r"(dst), "l"(src));
}

// ---------------- 0) convert x and W to fp16 ----------------
__global__ void split_all(const float* __restrict__ x,
                          const float* __restrict__ Wq, const float* __restrict__ Wk,
                          const float* __restrict__ Wv, const float* __restrict__ Ws,
                          int n)
{
    const int nx = n * (FDIM / 4);
    const int i = blockIdx.x * blockDim.x + threadIdx.x;
    if (i < nx) {
        float4 v = *(const float4*)(x + (size_t)i * 4);
        ushort4 h4;
        h4.x = __half_as_ushort(__float2half_rn(v.x));
        h4.y = __half_as_ushort(__float2half_rn(v.y));
        h4.z = __half_as_ushort(__float2half_rn(v.z));
        h4.w = __half_as_ushort(__float2half_rn(v.w));
        *(ushort4*)(g_xh + (size_t)i * 4) = h4;
    } else {
        const int j = i - nx;                 // over 512*32 float4s
        if (j >= 512 * (FDIM / 4)) return;
        const int m = j >> 12;
        const int r = j & 4095;
        const float* W = (m == 0) ? Wq : (m == 1) ? Wk : (m == 2) ? Wv : Ws;
        float4 v = *(const float4*)(W + (size_t)r * 4);
        ushort4 h4;
        h4.x = __half_as_ushort(__float2half_rn(v.x));
        h4.y = __half_as_ushort(__float2half_rn(v.y));
        h4.z = __half_as_ushort(__float2half_rn(v.z));
        h4.w = __half_as_ushort(__float2half_rn(v.w));
        *(ushort4*)(g_wh + (size_t)j * 4) = h4;
    }
}

// ---------------- 1) cp.async-pipelined fp16 mma GEMM (single pass, BK=32) ----------------
#define APAD32 40   // 80B row stride -> conflict-free frag loads
#define NT4 4       // 128 / 32

__device__ __forceinline__ void mma_fp16(float c[4], const uint32_t a[4], const uint32_t b[2]) {
    asm volatile(
        "mma.sync.aligned.m16n8k16.row.col.f32.f16.f16.f32 "
        "{%0,%1,%2,%3}, {%4,%5,%6,%7}, {%8,%9}, {%0,%1,%2,%3};"
        : "+f"(c[0]), "+f"(c[1]), "+f"(c[2]), "+f"(c[3])
        : "r"(a[0]), "r"(a[1]), "r"(a[2]), "r"(a[3]), "r"(b[0]), "r"(b[1]));
}

__global__ __launch_bounds__(256) void gemm_mma(
    const float* __restrict__ bq, const float* __restrict__ bk,
    const float* __restrict__ bv, const float* __restrict__ bs,
    int M)
{
    // [stage][array: A,B][128 rows * APAD32] = 40 KB
    __shared__ __half sm[2][2][128 * APAD32];

    const float* bias;
    switch (blockIdx.y) {
        case 0:  bias = bq; break;
        case 1:  bias = bk; break;
        case 2:  bias = bv; break;
        default: bias = bs; break;
    }
    const bool to_kv = (blockIdx.y == 1) || (blockIdx.y == 2);
    __half* outh = (blockIdx.y == 0) ? g_qh : g_skh;
    const int hsub = (blockIdx.y == 1) ? 0 : 4;
    const float oscale = (blockIdx.y == 0) ? 0.17677669529663687f : 1.0f;

    const int tid  = threadIdx.x;
    const int wid  = tid >> 5;
    const int lane = tid & 31;
    const int wm   = wid >> 2;
    const int wn   = wid & 3;
    const int m0   = blockIdx.x * 128;
    const int nb0  = blockIdx.y * 128;     // W row block
    const int qrow = lane >> 2;
    const int qk   = (lane & 3) * 2;

    // cp.async coords: per array per tile 512 chunks of 16B; 2 per thread
    const int f0 = tid, f1 = tid + 256;
    const int r0c = f0 >> 2, c0c = (f0 & 3) * 8;     // row, halves offset
    const int r1c = f1 >> 2, c1c = (f1 & 3) * 8;
    const uint32_t so0 = (uint32_t)(r0c * APAD32 + c0c) * 2;
    const uint32_t so1 = (uint32_t)(r1c * APAD32 + c1c) * 2;
    const size_t gaA0 = (size_t)(m0 + r0c) * FDIM + c0c;
    const size_t gaA1 = (size_t)(m0 + r1c) * FDIM + c1c;
    const size_t gaB0 = (size_t)(nb0 + r0c) * FDIM + c0c;
    const size_t gaB1 = (size_t)(nb0 + r1c) * FDIM + c1c;
    const uint32_t sb = smem_u32(&sm[0][0][0]);
    const uint32_t SA = 128 * APAD32 * 2;          // bytes per array
    const uint32_t SS = 2 * SA;                    // bytes per stage

    float c[4][4][4];
    #pragma unroll
    for (int mi = 0; mi < 4; mi++)
        #pragma unroll
        for (int nj = 0; nj < 4; nj++)
            #pragma unroll
            for (int r = 0; r < 4; r++) c[mi][nj][r] = 0.f;

    // prologue: tile 0 -> stage 0
    {
        cp16(sb + 0 * SA + so0, g_xh + gaA0);
        cp16(sb + 0 * SA + so1, g_xh + gaA1);
        cp16(sb + 1 * SA + so0, g_wh + gaB0);
        cp16(sb + 1 * SA + so1, g_wh + gaB1);
        asm volatile("cp.async.commit_group;");
    }

    for (int ct = 0; ct < NT4; ct++) {
        const int s = ct & 1;
        if (ct + 1 < NT4) {
            const int kt = (ct + 1) * 32;
            const uint32_t st = sb + ((ct + 1) & 1) * SS;
            cp16(st + 0 * SA + so0, g_xh + gaA0 + kt);
            cp16(st + 0 * SA + so1, g_xh + gaA1 + kt);
            cp16(st + 1 * SA + so0, g_wh + gaB0 + kt);
            cp16(st + 1 * SA + so1, g_wh + gaB1 + kt);
            asm volatile("cp.async.commit_group;");
            asm volatile("cp.async.wait_group 1;");
        } else {
            asm volatile("cp.async.wait_group 0;");
        }
        __syncthreads();

        const __half* Ab = sm[s][0];
        const __half* Bb = sm[s][1];
        #pragma unroll
        for (int ks = 0; ks < 2; ks++) {
            const int kb = ks * 16 + qk;
            uint32_t a[4][4], b[4][2];
            #pragma unroll
            for (int mi = 0; mi < 4; mi++) {
                const int row = wm * 64 + mi * 16 + qrow;
                a[mi][0] = *(const uint32_t*)(Ab + row * APAD32 + kb);
                a[mi][1] = *(const uint32_t*)(Ab + (row + 8) * APAD32 + kb);
                a[mi][2] = *(const uint32_t*)(Ab + row * APAD32 + kb + 8);
                a[mi][3] = *(const uint32_t*)(Ab + (row + 8) * APAD32 + kb + 8);
            }
            #pragma unroll
            for (int nj = 0; nj < 4; nj++) {
                const int col = wn * 32 + nj * 8 + qrow;
                b[nj][0] = *(const uint32_t*)(Bb + col * APAD32 + kb);
                b[nj][1] = *(const uint32_t*)(Bb + col * APAD32 + kb + 8);
            }
            #pragma unroll
            for (int mi = 0; mi < 4; mi++)
                #pragma unroll
                for (int nj = 0; nj < 4; nj++)
                    mma_fp16(c[mi][nj], a[mi], b[nj]);
        }
        __syncthreads();
    }

    float2 bj[4];
    #pragma unroll
    for (int nj = 0; nj < 4; nj++) {
        const int col = wn * 32 + nj * 8 + (lane & 3) * 2;
        bj[nj] = *(const float2*)(bias + col);
    }
    #pragma unroll
    for (int mi = 0; mi < 4; mi++) {
        const int r0 = m0 + wm * 64 + mi * 16 + qrow;
        #pragma unroll
        for (int nj = 0; nj < 4; nj++) {
            const int col = wn * 32 + nj * 8 + (lane & 3) * 2;
            const float v00 = (c[mi][nj][0] + bj[nj].x) * oscale;
            const float v01 = (c[mi][nj][1] + bj[nj].y) * oscale;
            const float v10 = (c[mi][nj][2] + bj[nj].x) * oscale;
            const float v11 = (c[mi][nj][3] + bj[nj].y) * oscale;
            if (to_kv) {
                const int off = ((col >> 2) << 3) + (col & 3) + hsub;
                if (r0 < M)
                    *(__half2*)(g_kv + (size_t)r0 * 256 + off) = __floats2half2_rn(v00, v01);
                if (r0 + 8 < M)
                    *(__half2*)(g_kv + (size_t)(r0 + 8) * 256 + off) = __floats2half2_rn(v10, v11);
            } else {
                if (r0 < M)
                    *(__half2*)(outh + (size_t)r0 * 128 + col) = __floats2half2_rn(v00, v01);
                if (r0 + 8 < M)
                    *(__half2*)(outh + (size_t)(r0 + 8) * 128 + col) = __floats2half2_rn(v10, v11);
            }
        }
    }
}

// ---------------- 2) CSR build ----------------
__global__ void zero_counts(int n)
{
    int i = blockIdx.x * blockDim.x + threadIdx.x;
    if (i < n) g_count[i] = 0;
}

__global__ void hist_kernel(const int* __restrict__ ei, int e)
{
    int i = blockIdx.x * blockDim.x + threadIdx.x;
    if (i < e) atomicAdd(&g_count[ei[e + i]], 1);
}

__global__ void scan_blocks(int n)
{
    __shared__ int sh[SCAN_BLK];
    const int t = threadIdx.x;
    const int i = blockIdx.x * SCAN_BLK + t;
    const int v = (i < n) ? g_count[i] : 0;
    sh[t] = v;
    __syncthreads();
    #pragma unroll
    for (int off = 1; off < SCAN_BLK; off <<= 1) {
        int u = (t >= off) ? sh[t - off] : 0;
        __syncthreads();
        sh[t] += u;
        __syncthreads();
    }
    if (i < n) g_rowptr[i] = sh[t] - v;
    if (t == SCAN_BLK - 1) g_bsum[blockIdx.x] = sh[t];
}

__global__ void scan_tops(int nb, int n)
{
    __shared__ int sh[SCAN_BLK];
    const int t = threadIdx.x;
    const int v = (t < nb) ? g_bsum[t] : 0;
    sh[t] = v;
    __syncthreads();
    #pragma unroll
    for (int off = 1; off < SCAN_BLK; off <<= 1) {
        int u = (t >= off) ? sh[t - off] : 0;
        __syncthreads();
        sh[t] += u;
        __syncthreads();
    }
    g_boff[t] = sh[t] - v;
    if (t == SCAN_BLK - 1) g_rowptr[n] = sh[t];
}

__global__ void add_offsets(int n)
{
    const int i = blockIdx.x * blockDim.x + threadIdx.x;
    if (i < n) {
        const int r = g_rowptr[i] + g_boff[i / SCAN_BLK];
        g_rowptr[i] = r;
        g_fill[i]   = r;
    }
}

__global__ void scatter_kernel(const int* __restrict__ ei, int e)
{
    int i = blockIdx.x * blockDim.x + threadIdx.x;
    if (i < e) {
        int dst  = ei[e + i];
        int slot = atomicAdd(&g_fill[dst], 1);
        g_esrc[slot] = ei[i];
    }
}

// ---------------- 3) fused attention aggregation: cp.async gather pipeline ----------------
#define EA_WARPS 8
__global__ __launch_bounds__(256) void edge_attn(float* __restrict__ out, int n)
{
    __shared__ char kvbuf[EA_WARPS][2][2048];   // 32 KB: 2 stages x 4 edges x 512B per warp

    const int wInB = threadIdx.x >> 5;
    const int lane = threadIdx.x & 31;
    const int node = blockIdx.x * EA_WARPS + wInB;
    if (node >= n) return;

    // hoist BOTH per-node loads (q and skip) before the edge loop so their
    // global latency overlaps the whole gather pipeline
    const uint2 qu = *(const uint2*)(g_qh + (size_t)node * 128 + lane * 4);
    const uint2 su = __ldg((const uint2*)(g_skh + (size_t)node * 128 + lane * 4));

    float4 q4;
    {
        const float2 qa = __half22float2(*(const __half2*)&qu.x);
        const float2 qb = __half22float2(*(const __half2*)&qu.y);
        q4 = make_float4(qa.x, qa.y, qb.x, qb.y);
    }

    float4 acc = make_float4(0.f, 0.f, 0.f, 0.f);
    float den = 0.f;

    const int beg = g_rowptr[node];
    const int end = g_rowptr[node + 1];
    const int ngrp = (end - beg) >> 2;
    const uint32_t sbase = smem_u32(&kvbuf[wInB][0][0]);

    int sB[4];
    if (ngrp > 0) {
        int sA[4];
        #pragma unroll
        for (int u = 0; u < 4; u++) sA[u] = __ldg(&g_esrc[beg + u]);
        #pragma unroll
        for (int u = 0; u < 4; u++)
            cp16(sbase + u * 512 + lane * 16, g_kv + (size_t)sA[u] * 256 + lane * 8);
        asm volatile("cp.async.commit_group;");
        if (ngrp > 1) {
            #pragma unroll
            for (int u = 0; u < 4; u++) sB[u] = __ldg(&g_esrc[beg + 4 + u]);
        }
    }

    for (int g = 0; g < ngrp; g++) {
        if (g + 1 < ngrp) {
            const uint32_t st = sbase + ((g + 1) & 1) * 2048;
            #pragma unroll
            for (int u = 0; u < 4; u++)
                cp16(st + u * 512 + lane * 16, g_kv + (size_t)sB[u] * 256 + lane * 8);
            asm volatile("cp.async.commit_group;");
            if (g + 2 < ngrp) {
                #pragma unroll
                for (int u = 0; u < 4; u++) sB[u] = __ldg(&g_esrc[beg + (g + 2) * 4 + u]);
            }
            asm volatile("cp.async.wait_group 1;");
        } else {
            asm volatile("cp.async.wait_group 0;");
        }

        const uint32_t cur = sbase + (g & 1) * 2048;
        uint4 kv[4];
        #pragma unroll
        for (int u = 0; u < 4; u++) {
            asm("ld.shared.v4.u32 {%0,%1,%2,%3}, [%4];"
                : "=r"(kv[u].x), "=r"(kv[u].y), "=r"(kv[u].z), "=r"(kv[u].w)
                : "r"(cur + u * 512 + lane * 16));
        }
        float p[4];
        #pragma unroll
        for (int u = 0; u < 4; u++) {
            const float2 ka = __half22float2(*(const __half2*)&kv[u].x);
            const float2 kb = __half22float2(*(const __half2*)&kv[u].y);
            p[u] = q4.x * ka.x + q4.y * ka.y + q4.z * kb.x + q4.w * kb.y;
        }
        #pragma unroll
        for (int u = 0; u < 4; u++) p[u] += __shfl_xor_sync(0xffffffffu, p[u], 1, 8);
        #pragma unroll
        for (int u = 0; u < 4; u++) p[u] += __shfl_xor_sync(0xffffffffu, p[u], 2, 8);
        #pragma unroll
        for (int u = 0; u < 4; u++) p[u] += __shfl_xor_sync(0xffffffffu, p[u], 4, 8);
        #pragma unroll
        for (int u = 0; u < 4; u++) {
            const float w = __expf(p[u]);
            const float2 va = __half22float2(*(const __half2*)&kv[u].z);
            const float2 vb = __half22float2(*(const __half2*)&kv[u].w);
            den += w;
            acc.x = fmaf(w, va.x, acc.x);
            acc.y = fmaf(w, va.y, acc.y);
            acc.z = fmaf(w, vb.x, acc.z);
            acc.w = fmaf(w, vb.y, acc.w);
        }
    }

    // tail (deg % 4) via direct loads
    for (int i = beg + ngrp * 4; i < end; i++) {
        const int s0 = __ldg(&g_esrc[i]);
        const uint4 kv0 = *(const uint4*)(g_kv + (size_t)s0 * 256 + lane * 8);
        const float2 ka = __half22float2(*(const __half2*)&kv0.x);
        const float2 kb = __half22float2(*(const __half2*)&kv0.y);
        float p0 = q4.x * ka.x + q4.y * ka.y + q4.z * kb.x + q4.w * kb.y;
        p0 += __shfl_xor_sync(0xffffffffu, p0, 1, 8);
        p0 += __shfl_xor_sync(0xffffffffu, p0, 2, 8);
        p0 += __shfl_xor_sync(0xffffffffu, p0, 4, 8);
        const float w = __expf(p0);
        const float2 va = __half22float2(*(const __half2*)&kv0.z);
        const float2 vb = __half22float2(*(const __half2*)&kv0.w);
        den += w;
        acc.x = fmaf(w, va.x, acc.x);
        acc.y = fmaf(w, va.y, acc.y);
        acc.z = fmaf(w, vb.x, acc.z);
        acc.w = fmaf(w, vb.y, acc.w);
    }

    const float inv = (den > 0.f) ? (1.0f / den) : 0.f;
    float4 sk;
    {
        const float2 sa = __half22float2(*(const __half2*)&su.x);
        const float2 sb2 = __half22float2(*(const __half2*)&su.y);
        sk = make_float4(sa.x, sa.y, sb2.x, sb2.y);
    }
    float4 o;
    o.x = fmaxf(fmaf(acc.x, inv, sk.x), 0.f);
    o.y = fmaxf(fmaf(acc.y, inv, sk.y), 0.f);
    o.z = fmaxf(fmaf(acc.z, inv, sk.z), 0.f);
    o.w = fmaxf(fmaf(acc.w, inv, sk.w), 0.f);
    *(float4*)(out + (size_t)node * 128 + lane * 4) = o;
}

// ---------------- host launcher ----------------
extern "C" void kernel_launch(void* const* d_in, const int* in_sizes, int n_in,
                              void* d_out, int out_size)
{
    const float* x  = (const float*)d_in[0];
    const int*   ei = (const int*)  d_in[1];
    const float* Wq = (const float*)d_in[2];
    const float* bq = (const float*)d_in[3];
    const float* Wk = (const float*)d_in[4];
    const float* bk = (const float*)d_in[5];
    const float* Wv = (const float*)d_in[6];
    const float* bv = (const float*)d_in[7];
    const float* Ws = (const float*)d_in[8];
    const float* bs = (const float*)d_in[9];
    float* out = (float*)d_out;

    const int n = in_sizes[0] / FDIM;   // 50000
    const int e = in_sizes[1] / 2;      // 800000
    const int nb = (n + SCAN_BLK - 1) / SCAN_BLK;

    // Side stream: CSR build overlaps convert + GEMM.
    cudaStream_t s2;
    cudaEvent_t ev0, ev1;
    cudaStreamCreateWithFlags(&s2, cudaStreamNonBlocking);
    cudaEventCreateWithFlags(&ev0, cudaEventDisableTiming);
    cudaEventCreateWithFlags(&ev1, cudaEventDisableTiming);

    cudaEventRecord(ev0, 0);
    cudaStreamWaitEvent(s2, ev0, 0);

    zero_counts<<<(n + 255) / 256, 256, 0, s2>>>(n);
    hist_kernel<<<(e + 255) / 256, 256, 0, s2>>>(ei, e);
    scan_blocks<<<nb, SCAN_BLK, 0, s2>>>(n);
    scan_tops<<<1, SCAN_BLK, 0, s2>>>(nb, n);
    add_offsets<<<(n + 255) / 256, 256, 0, s2>>>(n);
    scatter_kernel<<<(e + 255) / 256, 256, 0, s2>>>(ei, e);
    cudaEventRecord(ev1, s2);

    // fp16 convert, then pipelined GEMM, on main stream
    const int tot4 = n * (FDIM / 4) + 512 * (FDIM / 4);
    split_all<<<(tot4 + 255) / 256, 256>>>(x, Wq, Wk, Wv, Ws, n);
    dim3 gg((n + 127) / 128, 4);
    gemm_mma<<<gg, 256>>>(bq, bk, bv, bs, n);

    cudaStreamWaitEvent(0, ev1, 0);
    edge_attn<<<(n + EA_WARPS - 1) / EA_WARPS, 256>>>(out, n);
}